// round 1
// baseline (speedup 1.0000x reference)
#include <cuda_runtime.h>
#include <cstdint>

#define B_SIZE 4096
#define T_LEN  2048
#define H_DIM  32
#define THREADS 256
#define WARPS  (THREADS/32)
#define GRID   304

typedef unsigned long long ull;

__device__ int g_task_counter;

// ---- packed f32x2 helpers ----
__device__ __forceinline__ ull pk2(float a, float b) {
    ull r; asm("mov.b64 %0, {%1, %2};" : "=l"(r) : "f"(a), "f"(b)); return r;
}
__device__ __forceinline__ void upk2(ull v, float& a, float& b) {
    asm("mov.b64 {%0, %1}, %2;" : "=f"(a), "=f"(b) : "l"(v));
}
__device__ __forceinline__ void ffma2(ull& d, ull a, ull b) {
    asm("fma.rn.f32x2 %0, %1, %2, %0;" : "+l"(d) : "l"(a), "l"(b));
}

// ---- fast transcendentals (MUFU) ----
__device__ __forceinline__ float ex2f(float x) {
    float r; asm("ex2.approx.f32 %0, %1;" : "=f"(r) : "f"(x)); return r;
}
__device__ __forceinline__ float rcpf(float x) {
    float r; asm("rcp.approx.f32 %0, %1;" : "=f"(r) : "f"(x)); return r;
}
#define L2E 1.4426950408889634f
__device__ __forceinline__ float sigf(float z)  { return rcpf(1.f + ex2f(-L2E * z)); }
__device__ __forceinline__ float tanhf_(float z){ return fmaf(-2.f, rcpf(1.f + ex2f(2.f * L2E * z)), 1.f); }

__global__ void __launch_bounds__(THREADS, 1)
bilstm_kernel(const float* __restrict__ x,
              const int*   __restrict__ lengths,
              const float* __restrict__ w_ih,
              const float* __restrict__ w_hh,
              const float* __restrict__ b_ih,
              const float* __restrict__ b_hh,
              const float* __restrict__ fc_w,
              const float* __restrict__ fc_b,
              const float* __restrict__ fc2_w,
              const float* __restrict__ fc2_b,
              float* __restrict__ out)
{
    __shared__ float s_fcwT[32 * 64];   // fc_w transposed: [k][r] for conflict-free reads
    __shared__ float s_fc2[64];
    __shared__ __align__(16) float s_h[WARPS * 64];  // per-warp double-buffered h

    const int tid  = threadIdx.x;
    const int lane = tid & 31;
    const int wid  = tid >> 5;

    // block-shared FC weights (once per CTA)
    for (int i = tid; i < 32 * 64; i += THREADS) {
        int r = i & 63, k = i >> 6;
        s_fcwT[i] = fc_w[r * 32 + k];
    }
    if (tid < 64) s_fc2[tid] = fc2_w[tid];
    __syncthreads();

    // ---- per-lane recurrent weights in registers (loaded once) ----
    const int l = lane;
    const float bci = b_ih[l]      + b_hh[l];
    const float bcf = b_ih[32 + l] + b_hh[32 + l];
    const float bcg = b_ih[64 + l] + b_hh[64 + l];
    const float bco = b_ih[96 + l] + b_hh[96 + l];
    const float wxi = w_ih[l], wxf = w_ih[32 + l], wxg = w_ih[64 + l], wxo = w_ih[96 + l];

    ull wI[16], wF[16], wG[16], wO[16];
    {
        const ull* pI = (const ull*)(w_hh + (0  + l) * H_DIM);
        const ull* pF = (const ull*)(w_hh + (32 + l) * H_DIM);
        const ull* pG = (const ull*)(w_hh + (64 + l) * H_DIM);
        const ull* pO = (const ull*)(w_hh + (96 + l) * H_DIM);
        #pragma unroll
        for (int j = 0; j < 16; j++) { wI[j] = pI[j]; wF[j] = pF[j]; wG[j] = pG[j]; wO[j] = pO[j]; }
    }
    const float fc2b0 = fc2_b[0];
    const float fcb0  = fc_b[l];
    const float fcb1  = fc_b[32 + l];

    float* hb = s_h + wid * 64;

    // ---- dynamic task loop: one warp = one sequence at a time ----
    for (;;) {
        unsigned task = 0;
        if (lane == 0) task = (unsigned)atomicAdd(&g_task_counter, 1);
        task = __shfl_sync(0xffffffffu, task, 0);
        if (task >= B_SIZE) break;

        const int len = lengths[task];
        const float* xb = x + (size_t)task * T_LEN;

        float c = 0.f;
        int pb = 0;
        hb[lane] = 0.f;
        __syncwarp();

        int t = len - 1;
        float xv = __ldg(xb + t);
        while (t >= 0) {
            const int tn = (t > 0) ? (t - 1) : 0;
            float xn = __ldg(xb + tn);   // prefetch next x off the critical chain

            // gate accumulators: (even-k partial, odd-k partial); pre-activation in even slot
            ull ai = pk2(fmaf(xv, wxi, bci), 0.f);
            ull af = pk2(fmaf(xv, wxf, bcf), 0.f);
            ull ag = pk2(fmaf(xv, wxg, bcg), 0.f);
            ull ao = pk2(fmaf(xv, wxo, bco), 0.f);

            const ulonglong2* hp = (const ulonglong2*)(hb + pb);
            #pragma unroll
            for (int j = 0; j < 8; j++) {
                ulonglong2 q = hp[j];   // (h[4j],h[4j+1]) , (h[4j+2],h[4j+3])
                ffma2(ai, wI[2*j],     q.x); ffma2(af, wF[2*j],     q.x);
                ffma2(ag, wG[2*j],     q.x); ffma2(ao, wO[2*j],     q.x);
                ffma2(ai, wI[2*j + 1], q.y); ffma2(af, wF[2*j + 1], q.y);
                ffma2(ag, wG[2*j + 1], q.y); ffma2(ao, wO[2*j + 1], q.y);
            }
            float a0, a1;
            upk2(ai, a0, a1); const float gi = a0 + a1;
            upk2(af, a0, a1); const float gf = a0 + a1;
            upk2(ag, a0, a1); const float gg = a0 + a1;
            upk2(ao, a0, a1); const float go = a0 + a1;

            const float iv = sigf(gi);
            const float fv = sigf(gf);
            const float gv = tanhf_(gg);
            const float ov = sigf(go);
            c = fmaf(fv, c, iv * gv);
            const float hn = ov * tanhf_(c);

            pb ^= 32;
            hb[pb + lane] = hn;
            __syncwarp();
            xv = xn;
            --t;
        }

        // ---- FC head: lane l computes fc1 rows l and l+32 ----
        float u0 = fcb0, u1 = fcb1;
        #pragma unroll
        for (int k = 0; k < 32; k++) {
            const float hk = hb[pb + k];              // broadcast read
            u0 = fmaf(s_fcwT[k * 64 + l],      hk, u0);
            u1 = fmaf(s_fcwT[k * 64 + 32 + l], hk, u1);
        }
        // elu
        u0 = (u0 > 0.f) ? u0 : (ex2f(L2E * u0) - 1.f);
        u1 = (u1 > 0.f) ? u1 : (ex2f(L2E * u1) - 1.f);

        float part = u0 * s_fc2[l] + u1 * s_fc2[32 + l];
        #pragma unroll
        for (int s = 16; s; s >>= 1) part += __shfl_xor_sync(0xffffffffu, part, s);
        if (lane == 0) out[task] = sigf(part + fc2b0);
        __syncwarp();   // protect hb reuse across tasks
    }
}

__global__ void reset_counter_kernel() { g_task_counter = 0; }

extern "C" void kernel_launch(void* const* d_in, const int* in_sizes, int n_in,
                              void* d_out, int out_size)
{
    const float* x       = (const float*)d_in[0];
    const int*   lengths = (const int*)  d_in[1];
    const float* w_ih    = (const float*)d_in[2];
    const float* w_hh    = (const float*)d_in[3];
    const float* b_ih    = (const float*)d_in[4];
    const float* b_hh    = (const float*)d_in[5];
    const float* fc_w    = (const float*)d_in[6];
    const float* fc_b    = (const float*)d_in[7];
    const float* fc2_w   = (const float*)d_in[8];
    const float* fc2_b   = (const float*)d_in[9];
    float* out = (float*)d_out;

    reset_counter_kernel<<<1, 1>>>();
    bilstm_kernel<<<GRID, THREADS>>>(x, lengths, w_ih, w_hh, b_ih, b_hh,
                                     fc_w, fc_b, fc2_w, fc2_b, out);
}